// round 13
// baseline (speedup 1.0000x reference)
#include <cuda_runtime.h>
#include <cuda_fp16.h>
#include <cstdint>

#define NHEADS 32
#define HEAD 128
#define KVHEADS 8
#define SEQ 2048
#define BATCH 2
#define WINDOW 1024
#define SCALEF 0.08838834764831845f
#define LOG2E 1.4426950408889634f

#define BQ 128
#define BK 64
#define THREADS 512

// fp16 "paired" chunk layout (as R12): 32B chunk = 16 elems of a row,
// pair j = {e[2j],e[2j+1],e[2j+8],e[2j+9]} -> every fragment = 1 conflict-free LDS.64
#define OFF_Q 0        // 128 x 128 f16, 256B/row  = 32768
#define OFF_K 32768    // 64  x 128 f16            = 16384
#define OFF_V 49152    // V^T 128 dims x 64 keys   = 16384
#define OFF_PM 65536   // float[2][128] partial row max
#define OFF_PL 66560   // float[2][128] partial row sum
#define SMEM_BYTES 67584

static __device__ __forceinline__ uint32_t pk(float x, float y){
    __half2 h = __floats2half2_rn(x, y);
    return *(uint32_t*)&h;
}
static __device__ __forceinline__ float ex2f(float x){
    float y; asm("ex2.approx.f32 %0, %1;" : "=f"(y) : "f"(x)); return y;
}
#define MMA16(d, a0, a1, a2, a3, b0, b1) \
    asm volatile("mma.sync.aligned.m16n8k16.row.col.f32.f16.f16.f32 " \
        "{%0,%1,%2,%3}, {%4,%5,%6,%7}, {%8,%9}, {%0,%1,%2,%3};" \
        : "+f"((d)[0]), "+f"((d)[1]), "+f"((d)[2]), "+f"((d)[3]) \
        : "r"(a0), "r"(a1), "r"(a2), "r"(a3), "r"(b0), "r"(b1))
#define PAIR_BAR() asm volatile("bar.sync %0, 64;" :: "r"(pair + 1) : "memory")

__global__ void __launch_bounds__(THREADS, 1)
attn_h16p(const float* __restrict__ qg_, const float* __restrict__ kg_,
          const float* __restrict__ vg_, float* __restrict__ out)
{
    extern __shared__ char sm[];
    const int tid = threadIdx.x, w = tid >> 5, l = tid & 31;
    const int g = l >> 2, t = l & 3;
    const int pair = w >> 1, hf = w & 1;      // warp pair: shared rows, split keys
    const int q0 = blockIdx.x * BQ, h = blockIdx.y, b = blockIdx.z;
    const int kvh = h >> 2;

    const float* qg = qg_ + (size_t)b * SEQ * (NHEADS * HEAD) + (size_t)h * HEAD;
    const float* kg = kg_ + (size_t)b * SEQ * (KVHEADS * HEAD) + (size_t)kvh * HEAD;
    const float* vg = vg_ + (size_t)b * SEQ * (KVHEADS * HEAD) + (size_t)kvh * HEAD;

    // ---- stage Q: pre-scaled, f16, paired layout ----
    const float qsc = SCALEF * LOG2E;
#pragma unroll
    for (int i = tid; i < BQ * 8; i += THREADS){
        const int row = i >> 3, kc = i & 7;
        const float* gp = qg + (size_t)(q0 + row) * (NHEADS * HEAD) + kc * 16;
        float4 f0 = *(const float4*)(gp);
        float4 f1 = *(const float4*)(gp + 4);
        float4 f2 = *(const float4*)(gp + 8);
        float4 f3 = *(const float4*)(gp + 12);
        char* spp = sm + OFF_Q + row * 256 + ((kc ^ (row & 7)) << 5);
        uint4 u1, u2;
        u1.x = pk(f0.x * qsc, f0.y * qsc); u1.y = pk(f2.x * qsc, f2.y * qsc);
        u1.z = pk(f0.z * qsc, f0.w * qsc); u1.w = pk(f2.z * qsc, f2.w * qsc);
        u2.x = pk(f1.x * qsc, f1.y * qsc); u2.y = pk(f3.x * qsc, f3.y * qsc);
        u2.z = pk(f1.z * qsc, f1.w * qsc); u2.w = pk(f3.z * qsc, f3.w * qsc);
        *(uint4*)spp = u1; *(uint4*)(spp + 16) = u2;
    }

    float o[16][4];
#pragma unroll
    for (int n = 0; n < 16; n++){ o[n][0] = o[n][1] = o[n][2] = o[n][3] = 0.f; }
    float m0 = -1e30f, m1 = -1e30f, l0 = 0.f, l1 = 0.f;
    const int rloc0 = pair * 16 + g;          // CTA-local row
    const int r0 = q0 + rloc0, r1 = r0 + 8;

    float* pm = (float*)(sm + OFF_PM);
    float* pl = (float*)(sm + OFF_PL);

    int t_lo = 0;
    if (q0 >= WINDOW) t_lo = ((q0 - WINDOW + 1) >> 6) << 6;

    // staging task geometry (512 threads): K: 1 chunk; V: 2 transpose tasks
    const int krow = tid >> 3, kkc = tid & 7;
    const int kp1 = tid & 31,          dgA = tid >> 5;          // dims 0..60
    const int kp2 = kp1,               dgB = (tid + 512) >> 5;  // dims 64..124

    // ---- prefetch first K/V tile into packed registers ----
    uint4 ku1, ku2, vuA, vuB;
    {
        const int ts = t_lo;
        const float* gp = kg + (size_t)(ts + krow) * (KVHEADS * HEAD) + kkc * 16;
        float4 f0 = *(const float4*)(gp);
        float4 f1 = *(const float4*)(gp + 4);
        float4 f2 = *(const float4*)(gp + 8);
        float4 f3 = *(const float4*)(gp + 12);
        ku1.x = pk(f0.x, f0.y); ku1.y = pk(f2.x, f2.y);
        ku1.z = pk(f0.z, f0.w); ku1.w = pk(f2.z, f2.w);
        ku2.x = pk(f1.x, f1.y); ku2.y = pk(f3.x, f3.y);
        ku2.z = pk(f1.z, f1.w); ku2.w = pk(f3.z, f3.w);
        const float* va = vg + (size_t)(ts + 2 * kp1) * (KVHEADS * HEAD) + dgA * 4;
        float4 a = *(const float4*)va, c = *(const float4*)(va + KVHEADS * HEAD);
        vuA.x = pk(a.x, c.x); vuA.y = pk(a.y, c.y); vuA.z = pk(a.z, c.z); vuA.w = pk(a.w, c.w);
        const float* vb = vg + (size_t)(ts + 2 * kp2) * (KVHEADS * HEAD) + dgB * 4;
        a = *(const float4*)vb; c = *(const float4*)(vb + KVHEADS * HEAD);
        vuB.x = pk(a.x, c.x); vuB.y = pk(a.y, c.y); vuB.z = pk(a.z, c.z); vuB.w = pk(a.w, c.w);
    }

    for (int ts = t_lo; ts <= q0 + BK; ts += BK){
        __syncthreads();   // previous tile fully consumed
        // ---- STS prefetched K ----
        {
            char* spp = sm + OFF_K + krow * 256 + ((kkc ^ (krow & 7)) << 5);
            *(uint4*)spp = ku1; *(uint4*)(spp + 16) = ku2;
        }
        // ---- STS prefetched V (transposed scatter) ----
        {
            const int kc = kp1 >> 3, base = (kp1 & 3) * 8 + ((kp1 >> 2) & 1) * 4;
            int d0 = dgA * 4;
            *(uint32_t*)(sm + OFF_V + (d0    ) * 128 + ((kc ^ ((d0    ) & 3)) << 5) + base) = vuA.x;
            *(uint32_t*)(sm + OFF_V + (d0 + 1) * 128 + ((kc ^ ((d0 + 1) & 3)) << 5) + base) = vuA.y;
            *(uint32_t*)(sm + OFF_V + (d0 + 2) * 128 + ((kc ^ ((d0 + 2) & 3)) << 5) + base) = vuA.z;
            *(uint32_t*)(sm + OFF_V + (d0 + 3) * 128 + ((kc ^ ((d0 + 3) & 3)) << 5) + base) = vuA.w;
            d0 = dgB * 4;
            *(uint32_t*)(sm + OFF_V + (d0    ) * 128 + ((kc ^ ((d0    ) & 3)) << 5) + base) = vuB.x;
            *(uint32_t*)(sm + OFF_V + (d0 + 1) * 128 + ((kc ^ ((d0 + 1) & 3)) << 5) + base) = vuB.y;
            *(uint32_t*)(sm + OFF_V + (d0 + 2) * 128 + ((kc ^ ((d0 + 2) & 3)) << 5) + base) = vuB.z;
            *(uint32_t*)(sm + OFF_V + (d0 + 3) * 128 + ((kc ^ ((d0 + 3) & 3)) << 5) + base) = vuB.w;
        }
        __syncthreads();

        // ---- prefetch next tile (overlaps GEMM1/softmax/GEMM2) ----
        if (ts <= q0){
            const int nts = ts + BK;
            const float* gp = kg + (size_t)(nts + krow) * (KVHEADS * HEAD) + kkc * 16;
            float4 f0 = *(const float4*)(gp);
            float4 f1 = *(const float4*)(gp + 4);
            float4 f2 = *(const float4*)(gp + 8);
            float4 f3 = *(const float4*)(gp + 12);
            ku1.x = pk(f0.x, f0.y); ku1.y = pk(f2.x, f2.y);
            ku1.z = pk(f0.z, f0.w); ku1.w = pk(f2.z, f2.w);
            ku2.x = pk(f1.x, f1.y); ku2.y = pk(f3.x, f3.y);
            ku2.z = pk(f1.z, f1.w); ku2.w = pk(f3.z, f3.w);
            const float* va = vg + (size_t)(nts + 2 * kp1) * (KVHEADS * HEAD) + dgA * 4;
            float4 a = *(const float4*)va, c = *(const float4*)(va + KVHEADS * HEAD);
            vuA.x = pk(a.x, c.x); vuA.y = pk(a.y, c.y); vuA.z = pk(a.z, c.z); vuA.w = pk(a.w, c.w);
            const float* vb = vg + (size_t)(nts + 2 * kp2) * (KVHEADS * HEAD) + dgB * 4;
            a = *(const float4*)vb; c = *(const float4*)(vb + KVHEADS * HEAD);
            vuB.x = pk(a.x, c.x); vuB.y = pk(a.y, c.y); vuB.z = pk(a.z, c.z); vuB.w = pk(a.w, c.w);
        }

        // ---- GEMM1: S(16 rows x 32 keys per warp) = Q @ K^T ----
        float s[4][4];
#pragma unroll
        for (int n = 0; n < 4; n++){ s[n][0] = s[n][1] = s[n][2] = s[n][3] = 0.f; }
        {
            const char* qb = sm + OFF_Q + rloc0 * 256 + t * 8;
            const char* kb = sm + OFF_K + g * 256 + t * 8 + hf * 4 * 2048;
#pragma unroll
            for (int kc = 0; kc < 8; kc++){
                const int co = (kc ^ g) << 5;
                const uint2 A02 = *(const uint2*)(qb + co);
                const uint2 A13 = *(const uint2*)(qb + 2048 + co);
#pragma unroll
                for (int n = 0; n < 4; n++){
                    const uint2 B = *(const uint2*)(kb + n * 2048 + co);
                    MMA16(s[n], A02.x, A13.x, A02.y, A13.y, B.x, B.y);
                }
            }
        }

        // ---- mask + partial row max over this warp's 32 keys ----
        float mx0 = -1e30f, mx1 = -1e30f;
#pragma unroll
        for (int n = 0; n < 4; n++){
            const int c0 = ts + hf * 32 + n * 8 + 2 * t, c1 = c0 + 1;
            s[n][0] = ((c0 <= r0) && (r0 - c0 < WINDOW)) ? s[n][0] : -1e30f;
            s[n][1] = ((c1 <= r0) && (r0 - c1 < WINDOW)) ? s[n][1] : -1e30f;
            s[n][2] = ((c0 <= r1) && (r1 - c0 < WINDOW)) ? s[n][2] : -1e30f;
            s[n][3] = ((c1 <= r1) && (r1 - c1 < WINDOW)) ? s[n][3] : -1e30f;
            mx0 = fmaxf(mx0, fmaxf(s[n][0], s[n][1]));
            mx1 = fmaxf(mx1, fmaxf(s[n][2], s[n][3]));
        }
        mx0 = fmaxf(mx0, __shfl_xor_sync(0xffffffffu, mx0, 1));
        mx0 = fmaxf(mx0, __shfl_xor_sync(0xffffffffu, mx0, 2));
        mx1 = fmaxf(mx1, __shfl_xor_sync(0xffffffffu, mx1, 1));
        mx1 = fmaxf(mx1, __shfl_xor_sync(0xffffffffu, mx1, 2));
        if (t == 0){
            pm[hf * 128 + rloc0]     = mx0;
            pm[hf * 128 + rloc0 + 8] = mx1;
        }
        PAIR_BAR();
        mx0 = fmaxf(pm[rloc0],     pm[128 + rloc0]);
        mx1 = fmaxf(pm[rloc0 + 8], pm[128 + rloc0 + 8]);

        const float mn0 = fmaxf(m0, mx0), mn1 = fmaxf(m1, mx1);
        const float mc0 = fmaxf(mn0, -1e29f), mc1 = fmaxf(mn1, -1e29f);
        const float al0 = ex2f(m0 - mc0), al1 = ex2f(m1 - mc1);
        m0 = mn0; m1 = mn1;

        // ---- P in registers; partial row-sum ----
        uint32_t ph[4][2];
        float ps0 = 0.f, ps1 = 0.f;
#pragma unroll
        for (int n = 0; n < 4; n++){
            ph[n][0] = pk(ex2f(s[n][0] - mc0), ex2f(s[n][1] - mc0));
            ph[n][1] = pk(ex2f(s[n][2] - mc1), ex2f(s[n][3] - mc1));
            const float2 f0 = __half22float2(*(__half2*)&ph[n][0]);
            const float2 f1 = __half22float2(*(__half2*)&ph[n][1]);
            ps0 += f0.x + f0.y;
            ps1 += f1.x + f1.y;
        }
        ps0 += __shfl_xor_sync(0xffffffffu, ps0, 1);
        ps0 += __shfl_xor_sync(0xffffffffu, ps0, 2);
        ps1 += __shfl_xor_sync(0xffffffffu, ps1, 1);
        ps1 += __shfl_xor_sync(0xffffffffu, ps1, 2);
        if (t == 0){
            pl[hf * 128 + rloc0]     = ps0;
            pl[hf * 128 + rloc0 + 8] = ps1;
        }
        PAIR_BAR();
        l0 = l0 * al0 + pl[rloc0]     + pl[128 + rloc0];
        l1 = l1 * al1 + pl[rloc0 + 8] + pl[128 + rloc0 + 8];

#pragma unroll
        for (int n = 0; n < 16; n++){
            o[n][0] *= al0; o[n][1] *= al0; o[n][2] *= al1; o[n][3] *= al1;
        }

        // ---- GEMM2: O(16 x 128) += P(16 x 32, this warp's keys) @ V ----
        {
            const char* vb = sm + OFF_V + g * 128 + t * 8;
            const int co3 = g & 3;
#pragma unroll
            for (int kci = 0; kci < 2; kci++){
                const uint32_t a0 = ph[2 * kci][0],     a1 = ph[2 * kci][1];
                const uint32_t a2 = ph[2 * kci + 1][0], a3 = ph[2 * kci + 1][1];
                const int cs = ((hf * 2 + kci) ^ co3) << 5;
#pragma unroll
                for (int n = 0; n < 16; n++){
                    const uint2 B = *(const uint2*)(vb + n * 1024 + cs);
                    MMA16(o[n], a0, a1, a2, a3, B.x, B.y);
                }
            }
        }
    }

    // ---- epilogue: combine partial O across the warp pair, normalize, store ----
    __syncthreads();   // everyone done with Q/K/V smem; reuse as exchange buffer
    {
        // write the half I do NOT output (dims of partner's half)
        float* eb = (float*)(sm + (size_t)(pair * 2 + hf) * 4096);
        const int oh = (1 - hf) * 8;
#pragma unroll
        for (int n = 0; n < 8; n++){
            *(float2*)(eb + g * 64 + n * 8 + 2 * t)        = make_float2(o[oh + n][0], o[oh + n][1]);
            *(float2*)(eb + (g + 8) * 64 + n * 8 + 2 * t)  = make_float2(o[oh + n][2], o[oh + n][3]);
        }
        PAIR_BAR();
        const float* pb = (const float*)(sm + (size_t)(pair * 2 + (1 - hf)) * 4096);
        const float i0 = 1.f / l0, i1 = 1.f / l1;
        float* op0 = out + ((size_t)b * SEQ + r0) * (NHEADS * HEAD) + h * HEAD + hf * 64 + 2 * t;
        float* op1 = out + ((size_t)b * SEQ + r1) * (NHEADS * HEAD) + h * HEAD + hf * 64 + 2 * t;
        const int mh = hf * 8;
#pragma unroll
        for (int n = 0; n < 8; n++){
            const float2 e0 = *(const float2*)(pb + g * 64 + n * 8 + 2 * t);
            const float2 e1 = *(const float2*)(pb + (g + 8) * 64 + n * 8 + 2 * t);
            float2 v0, v1;
            v0.x = (o[mh + n][0] + e0.x) * i0; v0.y = (o[mh + n][1] + e0.y) * i0;
            v1.x = (o[mh + n][2] + e1.x) * i1; v1.y = (o[mh + n][3] + e1.y) * i1;
            *(float2*)(op0 + n * 8) = v0;
            *(float2*)(op1 + n * 8) = v1;
        }
    }
}

extern "C" void kernel_launch(void* const* d_in, const int* in_sizes, int n_in,
                              void* d_out, int out_size)
{
    const float* q = (const float*)d_in[0];
    const float* k = (const float*)d_in[1];
    const float* v = (const float*)d_in[2];
    float* out = (float*)d_out;

    cudaFuncSetAttribute(attn_h16p, cudaFuncAttributeMaxDynamicSharedMemorySize, SMEM_BYTES);
    dim3 grid(SEQ / BQ, NHEADS, BATCH);
    attn_h16p<<<grid, THREADS, SMEM_BYTES>>>(q, k, v, out);
}

// round 15
// speedup vs baseline: 2.3801x; 2.3801x over previous
#include <cuda_runtime.h>
#include <cuda_fp16.h>
#include <cstdint>

#define NHEADS 32
#define HEAD 128
#define KVHEADS 8
#define SEQ 2048
#define BATCH 2
#define WINDOW 1024
#define SCALEF 0.08838834764831845f
#define LOG2E 1.4426950408889634f

#define BQ 128
#define BK 64
#define THREADS 256

// fp16 tiles in "paired" chunk layout: each 32B chunk = 16 elems of one row,
// pair j (8B) = {e[16c+2j], e[16c+2j+1], e[16c+2j+8], e[16c+2j+9]}  (j=0..3)
// -> every m16n8k16 fragment load is ONE conflict-free LDS.64.
#define OFF_Q 0        // Q : 128 rows x 128 dims f16, 256B/row = 32768
#define OFF_K 32768    // K : 64 keys  x 128 dims f16, 256B/row = 16384
#define OFF_V 49152    // V^T: 128 dims x 64 keys f16, 128B/row = 16384
#define SMEM_BYTES 65536

static __device__ __forceinline__ uint32_t pk(float x, float y){
    __half2 h = __floats2half2_rn(x, y);
    return *(uint32_t*)&h;
}
static __device__ __forceinline__ float ex2f(float x){
    float y; asm("ex2.approx.f32 %0, %1;" : "=f"(y) : "f"(x)); return y;
}
#define MMA16(d, a0, a1, a2, a3, b0, b1) \
    asm volatile("mma.sync.aligned.m16n8k16.row.col.f32.f16.f16.f32 " \
        "{%0,%1,%2,%3}, {%4,%5,%6,%7}, {%8,%9}, {%0,%1,%2,%3};" \
        : "+f"((d)[0]), "+f"((d)[1]), "+f"((d)[2]), "+f"((d)[3]) \
        : "r"(a0), "r"(a1), "r"(a2), "r"(a3), "r"(b0), "r"(b1))

__global__ void __launch_bounds__(THREADS, 1)
attn_h16(const float* __restrict__ qg_, const float* __restrict__ kg_,
         const float* __restrict__ vg_, float* __restrict__ out)
{
    extern __shared__ char sm[];
    const int tid = threadIdx.x, w = tid >> 5, l = tid & 31;
    const int g = l >> 2, t = l & 3;
    const int q0 = blockIdx.x * BQ, h = blockIdx.y, b = blockIdx.z;
    const int kvh = h >> 2;

    const float* qg = qg_ + (size_t)b * SEQ * (NHEADS * HEAD) + (size_t)h * HEAD;
    const float* kg = kg_ + (size_t)b * SEQ * (KVHEADS * HEAD) + (size_t)kvh * HEAD;
    const float* vg = vg_ + (size_t)b * SEQ * (KVHEADS * HEAD) + (size_t)kvh * HEAD;

    // ---- stage Q: pre-scaled, f16, paired layout, chunk-swizzled ----
    const float qsc = SCALEF * LOG2E;
#pragma unroll
    for (int i = tid; i < BQ * 8; i += THREADS){
        const int row = i >> 3, kc = i & 7;
        const float* gp = qg + (size_t)(q0 + row) * (NHEADS * HEAD) + kc * 16;
        float4 f0 = *(const float4*)(gp);
        float4 f1 = *(const float4*)(gp + 4);
        float4 f2 = *(const float4*)(gp + 8);
        float4 f3 = *(const float4*)(gp + 12);
        char* spp = sm + OFF_Q + row * 256 + ((kc ^ (row & 7)) << 5);
        uint4 u1, u2;
        u1.x = pk(f0.x * qsc, f0.y * qsc); u1.y = pk(f2.x * qsc, f2.y * qsc);
        u1.z = pk(f0.z * qsc, f0.w * qsc); u1.w = pk(f2.z * qsc, f2.w * qsc);
        u2.x = pk(f1.x * qsc, f1.y * qsc); u2.y = pk(f3.x * qsc, f3.y * qsc);
        u2.z = pk(f1.z * qsc, f1.w * qsc); u2.w = pk(f3.z * qsc, f3.w * qsc);
        *(uint4*)spp = u1; *(uint4*)(spp + 16) = u2;
    }

    float o[16][4];
#pragma unroll
    for (int n = 0; n < 16; n++){ o[n][0] = o[n][1] = o[n][2] = o[n][3] = 0.f; }
    float m0 = -1e30f, m1 = -1e30f, l0 = 0.f, l1 = 0.f;
    const int r0 = q0 + w * 16 + g, r1 = r0 + 8;

    int t_lo = 0;
    if (q0 >= WINDOW) t_lo = ((q0 - WINDOW + 1) >> 6) << 6;

    // staging task geometry (256 threads): K: 2 chunk tasks; V: 4 transpose tasks
    const int kr0 = tid >> 3,        kc0 = tid & 7;          // K task 0
    const int kr1 = (tid + 256) >> 3, kc1 = tid & 7;         // K task 1
    const int vkp = tid & 31;                                 // V key-pair (all tasks)

    // prefetch register buffers (packed f16x2)
    uint4 ka1, ka2, kb1, kb2;      // K tasks 0,1 (16 regs)
    uint4 vu[4];                   // V tasks 0..3 (16 regs)

    // ---- prefetch first tile ----
    {
        const int ts = t_lo;
        const float* gp = kg + (size_t)(ts + kr0) * (KVHEADS * HEAD) + kc0 * 16;
        float4 f0 = *(const float4*)(gp), f1 = *(const float4*)(gp + 4);
        float4 f2 = *(const float4*)(gp + 8), f3 = *(const float4*)(gp + 12);
        ka1.x = pk(f0.x, f0.y); ka1.y = pk(f2.x, f2.y);
        ka1.z = pk(f0.z, f0.w); ka1.w = pk(f2.z, f2.w);
        ka2.x = pk(f1.x, f1.y); ka2.y = pk(f3.x, f3.y);
        ka2.z = pk(f1.z, f1.w); ka2.w = pk(f3.z, f3.w);
        gp = kg + (size_t)(ts + kr1) * (KVHEADS * HEAD) + kc1 * 16;
        f0 = *(const float4*)(gp); f1 = *(const float4*)(gp + 4);
        f2 = *(const float4*)(gp + 8); f3 = *(const float4*)(gp + 12);
        kb1.x = pk(f0.x, f0.y); kb1.y = pk(f2.x, f2.y);
        kb1.z = pk(f0.z, f0.w); kb1.w = pk(f2.z, f2.w);
        kb2.x = pk(f1.x, f1.y); kb2.y = pk(f3.x, f3.y);
        kb2.z = pk(f1.z, f1.w); kb2.w = pk(f3.z, f3.w);
#pragma unroll
        for (int j = 0; j < 4; j++){
            const int dg = (tid + j * 256) >> 5;
            const float* va = vg + (size_t)(ts + 2 * vkp) * (KVHEADS * HEAD) + dg * 4;
            const float4 a = *(const float4*)va;
            const float4 c = *(const float4*)(va + KVHEADS * HEAD);
            vu[j].x = pk(a.x, c.x); vu[j].y = pk(a.y, c.y);
            vu[j].z = pk(a.z, c.z); vu[j].w = pk(a.w, c.w);
        }
    }

    for (int ts = t_lo; ts <= q0 + BK; ts += BK){
        __syncthreads();   // previous tile fully consumed
        // ---- STS prefetched K ----
        {
            char* spp = sm + OFF_K + kr0 * 256 + ((kc0 ^ (kr0 & 7)) << 5);
            *(uint4*)spp = ka1; *(uint4*)(spp + 16) = ka2;
            spp = sm + OFF_K + kr1 * 256 + ((kc1 ^ (kr1 & 7)) << 5);
            *(uint4*)spp = kb1; *(uint4*)(spp + 16) = kb2;
        }
        // ---- STS prefetched V (transposed scatter) ----
        {
            const int kc = vkp >> 3, base = (vkp & 3) * 8 + ((vkp >> 2) & 1) * 4;
#pragma unroll
            for (int j = 0; j < 4; j++){
                const int d0 = ((tid + j * 256) >> 5) * 4;
                *(uint32_t*)(sm + OFF_V + (d0    ) * 128 + ((kc ^ ((d0    ) & 3)) << 5) + base) = vu[j].x;
                *(uint32_t*)(sm + OFF_V + (d0 + 1) * 128 + ((kc ^ ((d0 + 1) & 3)) << 5) + base) = vu[j].y;
                *(uint32_t*)(sm + OFF_V + (d0 + 2) * 128 + ((kc ^ ((d0 + 2) & 3)) << 5) + base) = vu[j].z;
                *(uint32_t*)(sm + OFF_V + (d0 + 3) * 128 + ((kc ^ ((d0 + 3) & 3)) << 5) + base) = vu[j].w;
            }
        }
        __syncthreads();

        // ---- prefetch next tile (LDG latency overlaps GEMM1/softmax/GEMM2) ----
        if (ts <= q0){
            const int nts = ts + BK;
            const float* gp = kg + (size_t)(nts + kr0) * (KVHEADS * HEAD) + kc0 * 16;
            float4 f0 = *(const float4*)(gp), f1 = *(const float4*)(gp + 4);
            float4 f2 = *(const float4*)(gp + 8), f3 = *(const float4*)(gp + 12);
            ka1.x = pk(f0.x, f0.y); ka1.y = pk(f2.x, f2.y);
            ka1.z = pk(f0.z, f0.w); ka1.w = pk(f2.z, f2.w);
            ka2.x = pk(f1.x, f1.y); ka2.y = pk(f3.x, f3.y);
            ka2.z = pk(f1.z, f1.w); ka2.w = pk(f3.z, f3.w);
            gp = kg + (size_t)(nts + kr1) * (KVHEADS * HEAD) + kc1 * 16;
            f0 = *(const float4*)(gp); f1 = *(const float4*)(gp + 4);
            f2 = *(const float4*)(gp + 8); f3 = *(const float4*)(gp + 12);
            kb1.x = pk(f0.x, f0.y); kb1.y = pk(f2.x, f2.y);
            kb1.z = pk(f0.z, f0.w); kb1.w = pk(f2.z, f2.w);
            kb2.x = pk(f1.x, f1.y); kb2.y = pk(f3.x, f3.y);
            kb2.z = pk(f1.z, f1.w); kb2.w = pk(f3.z, f3.w);
#pragma unroll
            for (int j = 0; j < 4; j++){
                const int dg = (tid + j * 256) >> 5;
                const float* va = vg + (size_t)(nts + 2 * vkp) * (KVHEADS * HEAD) + dg * 4;
                const float4 a = *(const float4*)va;
                const float4 c = *(const float4*)(va + KVHEADS * HEAD);
                vu[j].x = pk(a.x, c.x); vu[j].y = pk(a.y, c.y);
                vu[j].z = pk(a.z, c.z); vu[j].w = pk(a.w, c.w);
            }
        }

        // ---- GEMM1: S(16x64 per warp) = Q @ K^T, fp16 k16 ----
        float s[8][4];
#pragma unroll
        for (int n = 0; n < 8; n++){ s[n][0] = s[n][1] = s[n][2] = s[n][3] = 0.f; }
        {
            const char* qb = sm + OFF_Q + (w * 16 + g) * 256 + t * 8;
            const char* kb = sm + OFF_K + g * 256 + t * 8;
#pragma unroll
            for (int kc = 0; kc < 8; kc++){
                const int co = (kc ^ g) << 5;
                const uint2 A02 = *(const uint2*)(qb + co);            // a0,a2 (rows g)
                const uint2 A13 = *(const uint2*)(qb + 2048 + co);     // a1,a3 (rows g+8)
#pragma unroll
                for (int n = 0; n < 8; n++){
                    const uint2 B = *(const uint2*)(kb + n * 2048 + co);
                    MMA16(s[n], A02.x, A13.x, A02.y, A13.y, B.x, B.y);
                }
            }
        }

        // ---- mask + online softmax (warp-local rows) ----
        float mx0 = -1e30f, mx1 = -1e30f;
#pragma unroll
        for (int n = 0; n < 8; n++){
            const int c0 = ts + n * 8 + 2 * t, c1 = c0 + 1;
            s[n][0] = ((c0 <= r0) && (r0 - c0 < WINDOW)) ? s[n][0] : -1e30f;
            s[n][1] = ((c1 <= r0) && (r0 - c1 < WINDOW)) ? s[n][1] : -1e30f;
            s[n][2] = ((c0 <= r1) && (r1 - c0 < WINDOW)) ? s[n][2] : -1e30f;
            s[n][3] = ((c1 <= r1) && (r1 - c1 < WINDOW)) ? s[n][3] : -1e30f;
            mx0 = fmaxf(mx0, fmaxf(s[n][0], s[n][1]));
            mx1 = fmaxf(mx1, fmaxf(s[n][2], s[n][3]));
        }
        mx0 = fmaxf(mx0, __shfl_xor_sync(0xffffffffu, mx0, 1));
        mx0 = fmaxf(mx0, __shfl_xor_sync(0xffffffffu, mx0, 2));
        mx1 = fmaxf(mx1, __shfl_xor_sync(0xffffffffu, mx1, 1));
        mx1 = fmaxf(mx1, __shfl_xor_sync(0xffffffffu, mx1, 2));

        const float mn0 = fmaxf(m0, mx0), mn1 = fmaxf(m1, mx1);
        const float mc0 = fmaxf(mn0, -1e29f), mc1 = fmaxf(mn1, -1e29f);
        const float al0 = ex2f(m0 - mc0), al1 = ex2f(m1 - mc1);
        m0 = mn0; m1 = mn1;

        // P stays in registers: GEMM1 C-fragment == GEMM2 A-fragment (packed f16x2)
        uint32_t ph[8][2];
        float ps0 = 0.f, ps1 = 0.f;
#pragma unroll
        for (int n = 0; n < 8; n++){
            ph[n][0] = pk(ex2f(s[n][0] - mc0), ex2f(s[n][1] - mc0));
            ph[n][1] = pk(ex2f(s[n][2] - mc1), ex2f(s[n][3] - mc1));
            const float2 f0 = __half22float2(*(__half2*)&ph[n][0]);
            const float2 f1 = __half22float2(*(__half2*)&ph[n][1]);
            ps0 += f0.x + f0.y;
            ps1 += f1.x + f1.y;
        }
        ps0 += __shfl_xor_sync(0xffffffffu, ps0, 1);
        ps0 += __shfl_xor_sync(0xffffffffu, ps0, 2);
        ps1 += __shfl_xor_sync(0xffffffffu, ps1, 1);
        ps1 += __shfl_xor_sync(0xffffffffu, ps1, 2);
        l0 = l0 * al0 + ps0;
        l1 = l1 * al1 + ps1;

#pragma unroll
        for (int n = 0; n < 16; n++){
            o[n][0] *= al0; o[n][1] *= al0; o[n][2] *= al1; o[n][3] *= al1;
        }

        // ---- GEMM2: O(16x128 per warp) += P @ V ----
        {
            const char* vb = sm + OFF_V + g * 128 + t * 8;
            const int co = (g & 3);
#pragma unroll
            for (int kc = 0; kc < 4; kc++){
                const uint32_t a0 = ph[2 * kc][0],     a1 = ph[2 * kc][1];
                const uint32_t a2 = ph[2 * kc + 1][0], a3 = ph[2 * kc + 1][1];
                const int cs = (kc ^ co) << 5;
#pragma unroll
                for (int n = 0; n < 16; n++){
                    const uint2 B = *(const uint2*)(vb + n * 1024 + cs);
                    MMA16(o[n], a0, a1, a2, a3, B.x, B.y);
                }
            }
        }
    }

    // ---- epilogue: normalize + store ----
    const float i0 = 1.f / l0, i1 = 1.f / l1;
    float* op0 = out + ((size_t)b * SEQ + r0) * (NHEADS * HEAD) + h * HEAD + 2 * t;
    float* op1 = out + ((size_t)b * SEQ + r1) * (NHEADS * HEAD) + h * HEAD + 2 * t;
#pragma unroll
    for (int n = 0; n < 16; n++){
        float2 v0; v0.x = o[n][0] * i0; v0.y = o[n][1] * i0;
        float2 v1; v1.x = o[n][2] * i1; v1.y = o[n][3] * i1;
        *(float2*)(op0 + n * 8) = v0;
        *(float2*)(op1 + n * 8) = v1;
    }
}

extern "C" void kernel_launch(void* const* d_in, const int* in_sizes, int n_in,
                              void* d_out, int out_size)
{
    const float* q = (const float*)d_in[0];
    const float* k = (const float*)d_in[1];
    const float* v = (const float*)d_in[2];
    float* out = (float*)d_out;

    cudaFuncSetAttribute(attn_h16, cudaFuncAttributeMaxDynamicSharedMemorySize, SMEM_BYTES);
    dim3 grid(SEQ / BQ, NHEADS, BATCH);
    attn_h16<<<grid, THREADS, SMEM_BYTES>>>(q, k, v, out);
}